// round 2
// baseline (speedup 1.0000x reference)
#include <cuda_runtime.h>

// SAG: CSR SpMM neighbor aggregation, deg=16 fixed, D=48 fp32.
//   out[i][d] = sum_e X[col[e]][d]
//
// R2: L1tex-wavefront bound (R1 ncu: L1=67.9% > L2=50.6%, DRAM=12.8%).
// Vectorize the 192B row gather as 12 x LDG.128 across lanes 0..11 of a
// 16-lane node group: 1 load instruction per edge instead of 3, cutting
// L1tex wavefronts per edge-pair from 6 to 4 and LDG issue count by 3x.
// X (19.2 MB) stays L2-resident; edge loop fully unrolled for MLP.

#define D_FEAT 48
#define LANES_PER_NODE 16
#define VEC_LANES 12          // 12 float4 = 48 floats = one row

__global__ __launch_bounds__(256, 8)
void sag_kernel(const float* __restrict__ X,
                const int* __restrict__ row_pointers,
                const int* __restrict__ column_index,
                float* __restrict__ out,
                int n_nodes)
{
    const int tid  = blockIdx.x * blockDim.x + threadIdx.x;
    const int node = tid >> 4;                    // 16 lanes per node
    const int lane = tid & (LANES_PER_NODE - 1);  // 0..15

    if (node >= n_nodes) return;

    const int base = row_pointers[node];
    const int deg  = row_pointers[node + 1] - base;

    // Coalesced index prefetch: lane e holds edge e's neighbor id.
    int my_idx = 0;
    if (lane < deg) my_idx = column_index[base + lane];

    const float4* __restrict__ X4 = reinterpret_cast<const float4*>(X);
    float4 acc = make_float4(0.f, 0.f, 0.f, 0.f);
    const bool active = (lane < VEC_LANES);

    if (deg == LANES_PER_NODE) {
        // Fast path (always taken here): fully unrolled, ~12 independent
        // LDG.128 in flight per group.
        #pragma unroll
        for (int e = 0; e < LANES_PER_NODE; ++e) {
            const int idx = __shfl_sync(0xffffffffu, my_idx, e, LANES_PER_NODE);
            if (active) {
                const float4 v = __ldg(X4 + idx * VEC_LANES + lane);
                acc.x += v.x; acc.y += v.y; acc.z += v.z; acc.w += v.w;
            }
        }
    } else {
        // Generic fallback (robustness; deg is 16 by construction).
        for (int e = 0; e < deg; ++e) {
            int idx;
            if (e < LANES_PER_NODE) {
                idx = __shfl_sync(0xffffffffu, my_idx, e, LANES_PER_NODE);
            } else {
                idx = column_index[base + e];
            }
            if (active) {
                const float4 v = __ldg(X4 + idx * VEC_LANES + lane);
                acc.x += v.x; acc.y += v.y; acc.z += v.z; acc.w += v.w;
            }
        }
    }

    if (active) {
        reinterpret_cast<float4*>(out)[node * VEC_LANES + lane] = acc;
    }
}

extern "C" void kernel_launch(void* const* d_in, const int* in_sizes, int n_in,
                              void* d_out, int out_size)
{
    const float* X   = (const float*)d_in[0];
    const int*   rp  = (const int*)d_in[1];
    const int*   col = (const int*)d_in[2];
    float*       out = (float*)d_out;

    const int n_nodes = in_sizes[1] - 1;  // row_pointers has n+1 entries

    const int threads = 256;
    const int nodes_per_block = threads / LANES_PER_NODE;  // 16
    const int blocks = (n_nodes + nodes_per_block - 1) / nodes_per_block;

    sag_kernel<<<blocks, threads>>>(X, rp, col, out, n_nodes);
}